// round 17
// baseline (speedup 1.0000x reference)
#include <cuda_runtime.h>
#include <cuda_fp16.h>
#include <math.h>
#include <stdint.h>
#include <mma.h>

using namespace nvcuda;

// Problem constants (fixed shapes)
#define B_  16
#define T_  1000
#define TT_ 2000
#define F_  512
#define H_  512
#define HH_ 1024

// ---------------- device scratch ----------------
__device__ float g_wzh [B_ * TT_ * HH_];   // x_cat @ (scale.*[Wz;Wh])^T (bias added in scan)
__device__ float g_hseq[B_ * TT_ * H_ ];
__device__ float g_ln  [B_ * T_  * HH_];
__device__ float g_scale[HH_];
__device__ float g_bias [HH_];
// tagged mailbox: [parity][group][batch][slot=h index]; packet = (tag<<32)|f32
__device__ __align__(16) unsigned long long g_mail[2][8][2][512];

// ---------------- packed fp32x2 FMA ----------------
__device__ __forceinline__ float2 ffma2(float2 a, float2 b, float2 c) {
    float2 d;
    asm("fma.rn.f32x2 %0, %1, %2, %3;"
        : "=l"(reinterpret_cast<unsigned long long &>(d))
        : "l"(reinterpret_cast<unsigned long long &>(a)),
          "l"(reinterpret_cast<unsigned long long &>(b)),
          "l"(reinterpret_cast<unsigned long long &>(c)));
    return d;
}

// 8 fp32 -> 8 fp16, one 16B smem store
__device__ __forceinline__ void st_h8(__half* p, float4 v0, float4 v1) {
    __half2 h0 = __floats2half2_rn(v0.x, v0.y);
    __half2 h1 = __floats2half2_rn(v0.z, v0.w);
    __half2 h2 = __floats2half2_rn(v1.x, v1.y);
    __half2 h3 = __floats2half2_rn(v1.z, v1.w);
    uint4 u;
    u.x = *(unsigned*)&h0; u.y = *(unsigned*)&h1;
    u.z = *(unsigned*)&h2; u.w = *(unsigned*)&h3;
    *(uint4*)p = u;
}

// ---------------- prep ----------------
__global__ void prep_kernel(const float* __restrict__ bz, const float* __restrict__ bh,
                            const float* __restrict__ zg, const float* __restrict__ zb,
                            const float* __restrict__ zm, const float* __restrict__ zv,
                            const float* __restrict__ hg, const float* __restrict__ hb,
                            const float* __restrict__ hm, const float* __restrict__ hv) {
    int n = threadIdx.x;  // 1024 threads
    float sc, bi;
    if (n < 512) {
        sc = zg[n] * rsqrtf(zv[n] + 1e-5f);
        bi = (bz[n] - zm[n]) * sc + zb[n];
    } else {
        int j = n - 512;
        sc = hg[j] * rsqrtf(hv[j] + 1e-5f);
        bi = (bh[j] - hm[j]) * sc + hb[j];
    }
    g_scale[n] = sc;
    g_bias[n]  = bi;
    unsigned long long* mp = &g_mail[0][0][0][0];
    for (int i = n; i < 2 * 8 * 2 * 512; i += 1024) mp[i] = 0ull;
}

__global__ void dummy_kernel() {}

// ================= tiled fp16 GEMM core, 128x128 block (round-16 proven) =================
#define LDH 24
struct GemmSmem {
    char raw[24576];
    __device__ __forceinline__ __half* As(int st) { return (__half*)raw + st * 128 * LDH; }
    __device__ __forceinline__ __half* Bs(int st) { return (__half*)raw + 2 * 128 * LDH + st * 128 * LDH; }
};

#define GEMM_BODY128(K, BSCALE)                                                          \
    int a_r = tid >> 1;                                                                  \
    int a_k = (tid & 1) * 8;                                                             \
    int mw  = (wid & 3) * 32;                                                            \
    int nw  = (wid >> 2) * 64;                                                           \
    wmma::fragment<wmma::accumulator, 16, 16, 16, float> c_frag[2][4];                   \
    _Pragma("unroll")                                                                    \
    for (int mi = 0; mi < 2; mi++)                                                       \
        _Pragma("unroll")                                                                \
        for (int ni = 0; ni < 4; ni++) wmma::fill_fragment(c_frag[mi][ni], 0.f);         \
    float4 pa0, pa1, pb0, pb1;                                                           \
    pa0 = *(const float4*)(arow + a_k);                                                  \
    pa1 = *(const float4*)(arow + a_k + 4);                                              \
    pb0 = *(const float4*)(brow + a_k);                                                  \
    pb1 = *(const float4*)(brow + a_k + 4);                                              \
    pb0.x *= (BSCALE); pb0.y *= (BSCALE); pb0.z *= (BSCALE); pb0.w *= (BSCALE);          \
    pb1.x *= (BSCALE); pb1.y *= (BSCALE); pb1.z *= (BSCALE); pb1.w *= (BSCALE);          \
    st_h8(sm.As(0) + a_r * LDH + a_k, pa0, pa1);                                         \
    st_h8(sm.Bs(0) + a_r * LDH + a_k, pb0, pb1);                                         \
    __syncthreads();                                                                     \
    const int S = (K) / 16;                                                              \
    for (int s = 0; s < S; s++) {                                                        \
        int cur = s & 1;                                                                 \
        if (s + 1 < S) {                                                                 \
            int k0 = (s + 1) * 16;                                                       \
            pa0 = *(const float4*)(arow + k0 + a_k);                                     \
            pa1 = *(const float4*)(arow + k0 + a_k + 4);                                 \
            pb0 = *(const float4*)(brow + k0 + a_k);                                     \
            pb1 = *(const float4*)(brow + k0 + a_k + 4);                                 \
        }                                                                                \
        {                                                                                \
            wmma::fragment<wmma::matrix_b, 16, 16, 16, __half, wmma::col_major> b_frag[4]; \
            _Pragma("unroll")                                                            \
            for (int ni = 0; ni < 4; ni++)                                               \
                wmma::load_matrix_sync(b_frag[ni], sm.Bs(cur) + (nw + 16 * ni) * LDH, LDH); \
            _Pragma("unroll")                                                            \
            for (int mi = 0; mi < 2; mi++) {                                             \
                wmma::fragment<wmma::matrix_a, 16, 16, 16, __half, wmma::row_major> a_frag; \
                wmma::load_matrix_sync(a_frag, sm.As(cur) + (mw + 16 * mi) * LDH, LDH);  \
                _Pragma("unroll")                                                        \
                for (int ni = 0; ni < 4; ni++)                                           \
                    wmma::mma_sync(c_frag[mi][ni], a_frag, b_frag[ni], c_frag[mi][ni]);  \
            }                                                                            \
        }                                                                                \
        if (s + 1 < S) {                                                                 \
            int nxt = cur ^ 1;                                                           \
            pb0.x *= (BSCALE); pb0.y *= (BSCALE); pb0.z *= (BSCALE); pb0.w *= (BSCALE);  \
            pb1.x *= (BSCALE); pb1.y *= (BSCALE); pb1.z *= (BSCALE); pb1.w *= (BSCALE);  \
            st_h8(sm.As(nxt) + a_r * LDH + a_k, pa0, pa1);                               \
            st_h8(sm.Bs(nxt) + a_r * LDH + a_k, pb0, pb1);                               \
        }                                                                                \
        __syncthreads();                                                                 \
    }

// ---------------- phase 1: wzh_scaled = x_cat @ (scale .* [Wz;Wh])^T ----------------
__global__ __launch_bounds__(256, 2) void gemm_wzh(const float* __restrict__ x,
                                                   const float* __restrict__ Wz,
                                                   const float* __restrict__ Wh) {
    __shared__ __align__(16) GemmSmem sm;
    int tid = threadIdx.x;
    int wid = tid >> 5;
    int m0 = blockIdx.y * 128, n0 = blockIdx.x * 128;

    int m = m0 + (tid >> 1);
    int b = m / TT_;
    int tp = m - b * TT_;
    const float* arow = (tp < T_) ? (x + ((size_t)(b * T_ + tp) << 9))
                                  : (x + ((size_t)((15 - b) * T_ + (tp - T_)) << 9));
    int n = n0 + (tid >> 1);
    const float* brow = (n < 512) ? (Wz + ((size_t)n << 9))
                                  : (Wh + ((size_t)(n - 512) << 9));
    float bscale = g_scale[n];

    GEMM_BODY128(512, bscale)

#pragma unroll
    for (int mi = 0; mi < 2; mi++)
#pragma unroll
        for (int ni = 0; ni < 4; ni++)
            wmma::store_matrix_sync(
                g_wzh + (size_t)(m0 + mw + 16 * mi) * HH_ + n0 + nw + 16 * ni,
                c_frag[mi][ni], HH_, wmma::mem_row_major);
}

// ---------------- phase 2: persistent scan, batch-interleaved pipeline ----------------
// 8 groups x 16 CTAs; group g owns batches {2g, 2g+1}. Per step: phase A computes
// batch 0 (half matvec), publishes; phase B computes batch 1, publishes; each
// batch's L2 exchange latency hides under the other batch's compute.
// Pollers = upper 32 threads of each 64-thread chunk (overlaps gate warp's work).
__global__ __launch_bounds__(512, 1) void scan_kernel(const float* __restrict__ U) {
    __shared__ __align__(16) float h_sm[2][512];   // [batch][h]
    __shared__ float red[2][8][64];                // [phase][chunk][row]

    int t   = threadIdx.x;
    int grp = blockIdx.x >> 4;
    int ci  = blockIdx.x & 15;
    int b0  = grp * 2;

    int r = t & 63;              // local row 0..63 (0..31 z, 32..63 h)
    int c = t >> 6;              // k-chunk 0..7 (64 k each)
    int urow = (r < 32) ? (ci * 32 + r) : (512 + ci * 32 + (r - 32));

    const float2* Up = (const float2*)(U + (size_t)urow * 512 + c * 64);
    float2 Ureg[32];
#pragma unroll
    for (int q = 0; q < 32; q++) Ureg[q] = __ldg(&Up[q]);

    for (int idx = t; idx < 1024; idx += 512) ((float*)h_sm)[idx] = 0.f;

    // gate threads: t < 32, j = t, handle BOTH batches (phase A: b0, phase B: b0+1)
    int cz = ci * 32 + t, ch2 = 512 + ci * 32 + t;   // valid for t<32
    float hp0 = 0.f, hp1 = 0.f;
    float nz0 = 0.f, nh0 = 0.f, nz1 = 0.f, nh1 = 0.f;
    float bzr = 0.f, bhr = 0.f;
    if (t < 32) {
        bzr = g_bias[cz];
        bhr = g_bias[ch2];
        nz0 = __ldg(&g_wzh[(size_t)b0 * TT_ * HH_ + cz]) + bzr;
        nh0 = __ldg(&g_wzh[(size_t)b0 * TT_ * HH_ + ch2]) + bhr;
        nz1 = __ldg(&g_wzh[(size_t)(b0 + 1) * TT_ * HH_ + cz]) + bzr;
        nh1 = __ldg(&g_wzh[(size_t)(b0 + 1) * TT_ * HH_ + ch2]) + bhr;
    }
    // poller mapping: chunk c, r in [32,64) polls h slots c*64 + 2*(r-32), +1
    int slot = c * 64 + ((r - 32) << 1);   // meaningful only when r >= 32
    __syncthreads();

    for (int s = 0; s < TT_; s++) {
        unsigned tagp = (unsigned)(s + 1);
        int parp = (s + 1) & 1;

        // ===== phase A: batch 0 =====
        {
            float2 acc = make_float2(0.f, 0.f);
            const float4* hb = (const float4*)&h_sm[0][c * 64];
#pragma unroll
            for (int q = 0; q < 16; q++) {
                float4 v = hb[q];
                acc = ffma2(Ureg[2 * q],     make_float2(v.x, v.y), acc);
                acc = ffma2(Ureg[2 * q + 1], make_float2(v.z, v.w), acc);
            }
            red[0][c][r] = acc.x + acc.y;
        }
        __syncthreads();

        if (t < 32) {
            float uz = 0.f, uh = 0.f;
#pragma unroll
            for (int cc = 0; cc < 8; cc++) { uz += red[0][cc][t]; uh += red[0][cc][32 + t]; }
            float zt = __fdividef(1.f, 1.f + __expf(-(nz0 + uz)));
            float hc = fmaxf(nh0 + uh, 0.f);
            float hn = zt * hp0 + (1.f - zt) * hc;
            hp0 = hn;
            if (s + 1 < TT_) {
                unsigned long long pkt =
                    ((unsigned long long)tagp << 32) | (unsigned long long)__float_as_uint(hn);
                asm volatile("st.relaxed.gpu.u64 [%0], %1;"
                             :: "l"(&g_mail[parp][grp][0][ci * 32 + t]), "l"(pkt) : "memory");
            }
            __stcg(&g_hseq[((size_t)b0 * TT_ + s) * H_ + ci * 32 + t], hn);
            if (s + 1 < TT_) {
                nz0 = __ldg(&g_wzh[((size_t)b0 * TT_ + s + 1) * HH_ + cz]) + bzr;
                nh0 = __ldg(&g_wzh[((size_t)b0 * TT_ + s + 1) * HH_ + ch2]) + bhr;
            }
        }
        // poll batch-1 h(s-1) (published step s-1 phase B; latency hidden by phase A)
        if (s >= 1 && r >= 32) {
            unsigned tg = (unsigned)s;
            const unsigned long long* p = &g_mail[s & 1][grp][1][slot];
            unsigned long long v0, v1;
            do {
                asm volatile("ld.relaxed.gpu.v2.u64 {%0, %1}, [%2];"
                             : "=l"(v0), "=l"(v1) : "l"(p) : "memory");
            } while (((unsigned)(v0 >> 32) < tg) || ((unsigned)(v1 >> 32) < tg));
            h_sm[1][slot]     = __uint_as_float((unsigned)v0);
            h_sm[1][slot + 1] = __uint_as_float((unsigned)v1);
        }
        asm volatile("bar.sync %0, %1;" :: "r"(c + 1), "r"(64) : "memory");

        // ===== phase B: batch 1 =====
        {
            float2 acc = make_float2(0.f, 0.f);
            const float4* hb = (const float4*)&h_sm[1][c * 64];
#pragma unroll
            for (int q = 0; q < 16; q++) {
                float4 v = hb[q];
                acc = ffma2(Ureg[2 * q],     make_float2(v.x, v.y), acc);
                acc = ffma2(Ureg[2 * q + 1], make_float2(v.z, v.w), acc);
            }
            red[1][c][r] = acc.x + acc.y;
        }
        __syncthreads();

        if (t < 32) {
            float uz = 0.f, uh = 0.f;
#pragma unroll
            for (int cc = 0; cc < 8; cc++) { uz += red[1][cc][t]; uh += red[1][cc][32 + t]; }
            float zt = __fdividef(1.f, 1.f + __expf(-(nz1 + uz)));
            float hc = fmaxf(nh1 + uh, 0.f);
            float hn = zt * hp1 + (1.f - zt) * hc;
            hp1 = hn;
            if (s + 1 < TT_) {
                unsigned long long pkt =
                    ((unsigned long long)tagp << 32) | (unsigned long long)__float_as_uint(hn);
                asm volatile("st.relaxed.gpu.u64 [%0], %1;"
                             :: "l"(&g_mail[parp][grp][1][ci * 32 + t]), "l"(pkt) : "memory");
            }
            __stcg(&g_hseq[((size_t)(b0 + 1) * TT_ + s) * H_ + ci * 32 + t], hn);
            if (s + 1 < TT_) {
                nz1 = __ldg(&g_wzh[((size_t)(b0 + 1) * TT_ + s + 1) * HH_ + cz]) + bzr;
                nh1 = __ldg(&g_wzh[((size_t)(b0 + 1) * TT_ + s + 1) * HH_ + ch2]) + bhr;
            }
        }
        // poll batch-0 h(s) (published this step phase A; latency hidden by phase B)
        if (s + 1 < TT_ && r >= 32) {
            const unsigned long long* p = &g_mail[parp][grp][0][slot];
            unsigned long long v0, v1;
            do {
                asm volatile("ld.relaxed.gpu.v2.u64 {%0, %1}, [%2];"
                             : "=l"(v0), "=l"(v1) : "l"(p) : "memory");
            } while (((unsigned)(v0 >> 32) < tagp) || ((unsigned)(v1 >> 32) < tagp));
            h_sm[0][slot]     = __uint_as_float((unsigned)v0);
            h_sm[0][slot + 1] = __uint_as_float((unsigned)v1);
        }
        asm volatile("bar.sync %0, %1;" :: "r"(c + 1), "r"(64) : "memory");
    }
}

// ---------------- phase 3: LayerNorm (unchanged) ----------------
__global__ __launch_bounds__(256) void ln_kernel(const float* __restrict__ lng,
                                                 const float* __restrict__ lnb) {
    __shared__ float s_sum[8], s_sq[8];
    int row = blockIdx.x;
    int b = row / T_, tt = row - b * T_;
    int tid = threadIdx.x;
    int d = tid * 4;
    const float* base = (d < 512)
        ? (g_hseq + ((size_t)b * TT_ + tt) * H_ + d)
        : (g_hseq + ((size_t)(15 - b) * TT_ + T_ + tt) * H_ + (d - 512));
    float4 v = *(const float4*)base;
    float s = v.x + v.y + v.z + v.w;
    float q = v.x * v.x + v.y * v.y + v.z * v.z + v.w * v.w;
#pragma unroll
    for (int o = 16; o > 0; o >>= 1) {
        s += __shfl_down_sync(0xffffffffu, s, o);
        q += __shfl_down_sync(0xffffffffu, q, o);
    }
    int wid = tid >> 5, lid = tid & 31;
    if (lid == 0) { s_sum[wid] = s; s_sq[wid] = q; }
    __syncthreads();
    if (tid == 0) {
        float S = 0.f, Q = 0.f;
#pragma unroll
        for (int w = 0; w < 8; w++) { S += s_sum[w]; Q += s_sq[w]; }
        s_sum[0] = S; s_sq[0] = Q;
    }
    __syncthreads();
    float mu  = s_sum[0] * (1.f / 1024.f);
    float var = s_sq[0] * (1.f / 1024.f) - mu * mu;
    float inv = rsqrtf(var + 1e-5f);
    float4 g4 = *(const float4*)(lng + d);
    float4 b4 = *(const float4*)(lnb + d);
    float4 o;
    o.x = (v.x - mu) * inv * g4.x + b4.x;
    o.y = (v.y - mu) * inv * g4.y + b4.y;
    o.z = (v.z - mu) * inv * g4.z + b4.z;
    o.w = (v.w - mu) * inv * g4.w + b4.w;
    *(float4*)(g_ln + (size_t)row * HH_ + d) = o;
}

// ---------------- phase 4: out = tanh(ln @ pj_W^T + pj_b), fp16 wmma ----------------
__global__ __launch_bounds__(256, 2) void gemm_proj(const float* __restrict__ pjW,
                                                    const float* __restrict__ pjb,
                                                    float* __restrict__ out) {
    __shared__ __align__(16) GemmSmem sm;
    int tid = threadIdx.x;
    int wid = tid >> 5;
    int m0 = blockIdx.y * 128, n0 = blockIdx.x * 128;

    const float* arow = g_ln + (size_t)(m0 + (tid >> 1)) * HH_;
    const float* brow = pjW + (size_t)(n0 + (tid >> 1)) * HH_;

    GEMM_BODY128(1024, 1.0f)

    // bias slab in Bs(0): row n -> k0 = fp16(pjb[n0+n]), k1..15 = 0
    {
        int row = tid >> 1;
        int c8  = (tid & 1) * 8;
        uint4 zz = make_uint4(0u, 0u, 0u, 0u);
        *(uint4*)(sm.Bs(0) + row * LDH + c8) = zz;
        if (c8 == 0) sm.Bs(0)[row * LDH] = __float2half(pjb[n0 + row]);
    }
    __syncthreads();
    {
        wmma::fragment<wmma::matrix_a, 16, 16, 16, __half, wmma::row_major> ones;
        wmma::fill_fragment(ones, __float2half(1.0f));
#pragma unroll
        for (int ni = 0; ni < 4; ni++) {
            wmma::fragment<wmma::matrix_b, 16, 16, 16, __half, wmma::col_major> b_frag;
            wmma::load_matrix_sync(b_frag, sm.Bs(0) + (nw + 16 * ni) * LDH, LDH);
#pragma unroll
            for (int mi = 0; mi < 2; mi++)
                wmma::mma_sync(c_frag[mi][ni], ones, b_frag, c_frag[mi][ni]);
        }
    }
#pragma unroll
    for (int mi = 0; mi < 2; mi++)
#pragma unroll
        for (int ni = 0; ni < 4; ni++) {
#pragma unroll
            for (int e = 0; e < c_frag[mi][ni].num_elements; e++)
                c_frag[mi][ni].x[e] = tanhf(c_frag[mi][ni].x[e]);
            wmma::store_matrix_sync(
                out + (size_t)(m0 + mw + 16 * mi) * HH_ + n0 + nw + 16 * ni,
                c_frag[mi][ni], HH_, wmma::mem_row_major);
        }
}

// ---------------- tail: x_len pass-through ----------------
__global__ void tail_kernel(const int* __restrict__ xlen, float* __restrict__ out) {
    int t = threadIdx.x;
    if (t < B_) out[(size_t)B_ * T_ * HH_ + t] = (float)xlen[t];
}

extern "C" void kernel_launch(void* const* d_in, const int* in_sizes, int n_in,
                              void* d_out, int out_size) {
    const float* x   = (const float*)d_in[0];
    const int*   xl  = (const int*)  d_in[1];
    const float* Wz  = (const float*)d_in[2];
    const float* bz  = (const float*)d_in[3];
    const float* Wh  = (const float*)d_in[4];
    const float* bh  = (const float*)d_in[5];
    const float* U   = (const float*)d_in[6];
    const float* zg  = (const float*)d_in[7];
    const float* zb  = (const float*)d_in[8];
    const float* zm  = (const float*)d_in[9];
    const float* zv  = (const float*)d_in[10];
    const float* hg  = (const float*)d_in[11];
    const float* hb  = (const float*)d_in[12];
    const float* hm  = (const float*)d_in[13];
    const float* hv  = (const float*)d_in[14];
    const float* lng = (const float*)d_in[15];
    const float* lnb = (const float*)d_in[16];
    const float* pjW = (const float*)d_in[17];
    const float* pjb = (const float*)d_in[18];
    float* out = (float*)d_out;

    prep_kernel<<<1, 1024>>>(bz, bh, zg, zb, zm, zv, hg, hb, hm, hv);
    dummy_kernel<<<1, 32>>>();
    gemm_wzh<<<dim3(8, 250), 256>>>(x, Wz, Wh);
    scan_kernel<<<128, 512>>>(U);        // launch #4 -> ncu captures the scan
    ln_kernel<<<16000, 256>>>(lng, lnb);
    gemm_proj<<<dim3(8, 125), 256>>>(pjW, pjb, out);
    if (out_size >= B_ * T_ * HH_ + B_) {
        tail_kernel<<<1, 32>>>(xl, out);
    }
    (void)in_sizes; (void)n_in;
}